// round 4
// baseline (speedup 1.0000x reference)
#include <cuda_runtime.h>

#define NMAX 50000

// ---- scratch (static __device__ per allocation rules) ----
// per-node src-side pack: [2n] = a_src(4 heads), [2n+1] = {x0, x1, 0, 0}
__device__ __align__(32) float4 g_srcpack[NMAX * 2];
__device__ float4 g_adst[NMAX];         // a_dst per head (4)
__device__ float4 g_accum[NMAX * 3];    // [denom(4)][T0(4)][T1(4)] per node
__device__ float  g_consts[20];         // s0[4] s1[4] d0[4] d1[4] g[4]
__device__ float  g_easum;

// Warp-local computation of the 20 head constants (no shared mem, no barriers).
// cs[0..3]=s0, [4..7]=s1, [8..11]=d0, [12..15]=d1, [16..19]=g  (indexed by head)
__device__ __forceinline__ void warp_consts(const float* __restrict__ W,
                                            const float* __restrict__ att_src,
                                            const float* __restrict__ att_dst,
                                            const float* __restrict__ W_edge,
                                            const float* __restrict__ att_edge,
                                            int lane, float* cs) {
    #pragma unroll
    for (int h = 0; h < 4; h++) {
        float a0 = 0.f, a1 = 0.f, a2 = 0.f, a3 = 0.f, a4 = 0.f;
        #pragma unroll
        for (int k = 0; k < 2; k++) {
            int t = h * 64 + lane + k * 32;
            float w0 = __ldg(&W[2 * t]), w1 = __ldg(&W[2 * t + 1]);
            float as = __ldg(&att_src[t]), ad = __ldg(&att_dst[t]);
            a0 += w0 * as;
            a1 += w1 * as;
            a2 += w0 * ad;
            a3 += w1 * ad;
            a4 += __ldg(&W_edge[t]) * __ldg(&att_edge[t]);
        }
        #pragma unroll
        for (int o = 16; o; o >>= 1) {
            a0 += __shfl_xor_sync(0xffffffffu, a0, o);
            a1 += __shfl_xor_sync(0xffffffffu, a1, o);
            a2 += __shfl_xor_sync(0xffffffffu, a2, o);
            a3 += __shfl_xor_sync(0xffffffffu, a3, o);
            a4 += __shfl_xor_sync(0xffffffffu, a4, o);
        }
        cs[0 + h]  = a0;
        cs[4 + h]  = a1;
        cs[8 + h]  = a2;
        cs[12 + h] = a3;
        cs[16 + h] = a4;
    }
}

// K0: constants (per-warp, barrier-free) + per-node pack + accumulator zero
__global__ void k_prep(const float* __restrict__ x, const float* __restrict__ W,
                       const float* __restrict__ att_src, const float* __restrict__ att_dst,
                       const float* __restrict__ W_edge, const float* __restrict__ att_edge,
                       int N) {
    int t = threadIdx.x;
    int lane = t & 31;
    float cs[20];
    warp_consts(W, att_src, att_dst, W_edge, att_edge, lane, cs);

    if (blockIdx.x == 0 && t < 32) {
        if (lane < 20) g_consts[lane] = cs[lane];
        if (lane == 0) g_easum = 0.f;
    }

    int n = blockIdx.x * blockDim.x + t;
    if (n >= N) return;
    float x0 = x[2 * n], x1 = x[2 * n + 1];
    float4 as4, ad4;
    as4.x = x0 * cs[0] + x1 * cs[4];
    as4.y = x0 * cs[1] + x1 * cs[5];
    as4.z = x0 * cs[2] + x1 * cs[6];
    as4.w = x0 * cs[3] + x1 * cs[7];
    ad4.x = x0 * cs[8]  + x1 * cs[12];
    ad4.y = x0 * cs[9]  + x1 * cs[13];
    ad4.z = x0 * cs[10] + x1 * cs[14];
    ad4.w = x0 * cs[11] + x1 * cs[15];
    g_srcpack[2 * n]     = as4;
    g_srcpack[2 * n + 1] = make_float4(x0, x1, 0.f, 0.f);
    g_adst[n] = ad4;
    float4 z = make_float4(0.f, 0.f, 0.f, 0.f);
    g_accum[n * 3 + 0] = z;
    g_accum[n * 3 + 1] = z;
    g_accum[n * 3 + 2] = z;
}

__device__ __forceinline__ void red_v4(float4* p, float a, float b, float c, float d) {
    asm volatile("red.global.add.v4.f32 [%0], {%1,%2,%3,%4};"
                 :: "l"(p), "f"(a), "f"(b), "f"(c), "f"(d) : "memory");
}

__device__ __forceinline__ void edge_body(int src, int dst, float w, int N,
                                          float g0, float g1, float g2, float g3) {
    if ((unsigned)src >= (unsigned)N || (unsigned)dst >= (unsigned)N) return;
    float4 as = g_srcpack[2 * src];
    float4 xs = g_srcpack[2 * src + 1];
    float4 ad = g_adst[dst];
    float a0 = as.x + ad.x + w * g0; a0 = fmaxf(a0, 0.2f * a0);
    float a1 = as.y + ad.y + w * g1; a1 = fmaxf(a1, 0.2f * a1);
    float a2 = as.z + ad.z + w * g2; a2 = fmaxf(a2, 0.2f * a2);
    float a3 = as.w + ad.w + w * g3; a3 = fmaxf(a3, 0.2f * a3);
    float e0 = __expf(a0), e1 = __expf(a1), e2 = __expf(a2), e3 = __expf(a3);
    float4* base = &g_accum[dst * 3];
    red_v4(base,     e0,        e1,        e2,        e3);
    red_v4(base + 1, e0 * xs.x, e1 * xs.x, e2 * xs.x, e3 * xs.x);
    red_v4(base + 2, e0 * xs.y, e1 * xs.y, e2 * xs.y, e3 * xs.y);
}

// K1: edge pass — 2 edges/thread, loads front-batched for MLP; + easum reduce
__global__ void k_edge(const int* __restrict__ ei, const float* __restrict__ ea,
                       int E, int N) {
    float g0 = g_consts[16], g1 = g_consts[17], g2 = g_consts[18], g3 = g_consts[19];
    int base = blockIdx.x * (blockDim.x * 2) + threadIdx.x;
    int e0 = base;
    int e1 = base + blockDim.x;
    float wsum = 0.f;

    int s0 = 0, d0 = 0, s1 = 0, d1 = 0;
    float w0 = 0.f, w1 = 0.f;
    bool v0 = e0 < E, v1 = e1 < E;
    if (v0) { s0 = __ldg(&ei[e0]); d0 = __ldg(&ei[E + e0]); w0 = __ldg(&ea[e0]); }
    if (v1) { s1 = __ldg(&ei[e1]); d1 = __ldg(&ei[E + e1]); w1 = __ldg(&ea[e1]); }
    if (v0) { wsum += w0; edge_body(s0, d0, w0, N, g0, g1, g2, g3); }
    if (v1) { wsum += w1; edge_body(s1, d1, w1, N, g0, g1, g2, g3); }

    // block-reduce wsum -> g_easum
    #pragma unroll
    for (int o = 16; o; o >>= 1) wsum += __shfl_down_sync(0xffffffffu, wsum, o);
    __shared__ float sh[8];
    if ((threadIdx.x & 31) == 0) sh[threadIdx.x >> 5] = wsum;
    __syncthreads();
    if (threadIdx.x == 0) {
        float s = 0.f;
        #pragma unroll
        for (int i = 0; i < 8; i++) s += sh[i];
        atomicAdd(&g_easum, s);
    }
}

// K2: per-node expansion to [N, 256], self-loop folded in analytically.
__global__ void k_out(const float* __restrict__ W, const float* __restrict__ bias,
                      float* __restrict__ out, int N, float invE) {
    int t = threadIdx.x;
    int sub = t & 63;
    int hc0 = sub * 4;
    int h = hc0 >> 6;
    const float4* W4 = (const float4*)W;
    float4 wa = W4[sub * 2];
    float4 wb = W4[sub * 2 + 1];
    float4 b4 = ((const float4*)bias)[sub];
    float mean = g_easum * invE;
    float gh = g_consts[16 + h];

    int n = blockIdx.x * 4 + (t >> 6);
    if (n >= N) return;

    float4 as4 = g_srcpack[2 * n];
    float4 xs  = g_srcpack[2 * n + 1];
    float4 ad4 = g_adst[n];
    float4 d4  = g_accum[n * 3 + 0];
    float4 t04 = g_accum[n * 3 + 1];
    float4 t14 = g_accum[n * 3 + 2];
    float ash = (h == 0) ? as4.x : (h == 1) ? as4.y : (h == 2) ? as4.z : as4.w;
    float adh = (h == 0) ? ad4.x : (h == 1) ? ad4.y : (h == 2) ? ad4.z : ad4.w;
    float dh  = (h == 0) ? d4.x  : (h == 1) ? d4.y  : (h == 2) ? d4.z  : d4.w;
    float t0h = (h == 0) ? t04.x : (h == 1) ? t04.y : (h == 2) ? t04.z : t04.w;
    float t1h = (h == 0) ? t14.x : (h == 1) ? t14.y : (h == 2) ? t14.z : t14.w;

    float a = ash + adh + mean * gh;   // self-loop logit
    a = fmaxf(a, 0.2f * a);
    float ws = __expf(a);
    float rdenom = 1.0f / (dh + ws);
    float T0 = (t0h + ws * xs.x) * rdenom;
    float T1 = (t1h + ws * xs.y) * rdenom;

    float4 o;
    o.x = T0 * wa.x + T1 * wa.y + b4.x;
    o.y = T0 * wa.z + T1 * wa.w + b4.y;
    o.z = T0 * wb.x + T1 * wb.y + b4.z;
    o.w = T0 * wb.z + T1 * wb.w + b4.w;
    ((float4*)out)[(size_t)n * 64 + sub] = o;
}

extern "C" void kernel_launch(void* const* d_in, const int* in_sizes, int n_in,
                              void* d_out, int out_size) {
    const float* x        = (const float*)d_in[0];
    const int*   ei       = (const int*)d_in[1];     // int32 (JAX x64 off)
    const float* ea       = (const float*)d_in[2];
    const float* W        = (const float*)d_in[3];
    const float* att_src  = (const float*)d_in[4];
    const float* att_dst  = (const float*)d_in[5];
    const float* W_edge   = (const float*)d_in[6];
    const float* att_edge = (const float*)d_in[7];
    const float* bias     = (const float*)d_in[8];
    int N = in_sizes[0] / 2;
    int E = in_sizes[2];
    float* out = (float*)d_out;

    k_prep<<<(N + 255) / 256, 256>>>(x, W, att_src, att_dst, W_edge, att_edge, N);
    k_edge<<<(E + 511) / 512, 256>>>(ei, ea, E, N);
    k_out<<<(N + 3) / 4, 256>>>(W, bias, out, N, 1.0f / (float)E);
}

// round 5
// speedup vs baseline: 1.1033x; 1.1033x over previous
#include <cuda_runtime.h>

#define NMAX 50000
#define ACC4 (NMAX * 3)   // float4 count in accumulator

// ---- scratch (static __device__ per allocation rules) ----
__device__ float4 g_accum[ACC4];   // per node: [denom(4)][T0(4)][T1(4)]
__device__ float  g_consts[20];    // s0[4] s1[4] d0[4] d1[4] g[4]
__device__ float  g_easum;

// K0: zero accumulators (all blocks, grid-stride) + block 0 computes constants.
__global__ void k_init(const float* __restrict__ W, const float* __restrict__ att_src,
                       const float* __restrict__ att_dst, const float* __restrict__ W_edge,
                       const float* __restrict__ att_edge) {
    int t = threadIdx.x;
    // zeroing
    float4 z = make_float4(0.f, 0.f, 0.f, 0.f);
    for (int i = blockIdx.x * blockDim.x + t; i < ACC4; i += gridDim.x * blockDim.x)
        g_accum[i] = z;

    if (blockIdx.x != 0) return;
    // constants: 256 threads = H*C, shared reduction
    __shared__ float sh[5][256];
    int h = t >> 6;
    float w0 = W[2 * t], w1 = W[2 * t + 1];
    float as = att_src[t], ad = att_dst[t];
    sh[0][t] = w0 * as;
    sh[1][t] = w1 * as;
    sh[2][t] = w0 * ad;
    sh[3][t] = w1 * ad;
    sh[4][t] = W_edge[t] * att_edge[t];
    __syncthreads();
    for (int off = 32; off >= 1; off >>= 1) {
        if ((t & 63) < off) {
            #pragma unroll
            for (int k = 0; k < 5; k++) sh[k][t] += sh[k][t + off];
        }
        __syncthreads();
    }
    if ((t & 63) == 0) {
        #pragma unroll
        for (int k = 0; k < 5; k++) g_consts[k * 4 + h] = sh[k][t];
    }
    if (t == 0) g_easum = 0.f;
}

__device__ __forceinline__ void red_v4(float4* p, float a, float b, float c, float d) {
    asm volatile("red.global.add.v4.f32 [%0], {%1,%2,%3,%4};"
                 :: "l"(p), "f"(a), "f"(b), "f"(c), "f"(d) : "memory");
}

struct C20 {
    float s0[4], s1[4], d0[4], d1[4], g[4];
};

__device__ __forceinline__ void edge_body(const float2* __restrict__ x2,
                                          int src, int dst, float w, int N, const C20& c) {
    if ((unsigned)src >= (unsigned)N || (unsigned)dst >= (unsigned)N) return;
    float2 xs = __ldg(&x2[src]);
    float2 xd = __ldg(&x2[dst]);
    #pragma unroll 1
    for (int dummy = 0; dummy < 1; dummy++) {}
    float e0, e1, e2, e3;
    {
        float a0 = xs.x * c.s0[0] + xs.y * c.s1[0] + xd.x * c.d0[0] + xd.y * c.d1[0] + w * c.g[0];
        float a1 = xs.x * c.s0[1] + xs.y * c.s1[1] + xd.x * c.d0[1] + xd.y * c.d1[1] + w * c.g[1];
        float a2 = xs.x * c.s0[2] + xs.y * c.s1[2] + xd.x * c.d0[2] + xd.y * c.d1[2] + w * c.g[2];
        float a3 = xs.x * c.s0[3] + xs.y * c.s1[3] + xd.x * c.d0[3] + xd.y * c.d1[3] + w * c.g[3];
        a0 = fmaxf(a0, 0.2f * a0);
        a1 = fmaxf(a1, 0.2f * a1);
        a2 = fmaxf(a2, 0.2f * a2);
        a3 = fmaxf(a3, 0.2f * a3);
        e0 = __expf(a0); e1 = __expf(a1); e2 = __expf(a2); e3 = __expf(a3);
    }
    float4* base = &g_accum[dst * 3];
    red_v4(base,     e0,        e1,        e2,        e3);
    red_v4(base + 1, e0 * xs.x, e1 * xs.x, e2 * xs.x, e3 * xs.x);
    red_v4(base + 2, e0 * xs.y, e1 * xs.y, e2 * xs.y, e3 * xs.y);
}

// K1: edge pass — 2 edges/thread, front-batched loads; + easum block reduce
__global__ void k_edge(const int* __restrict__ ei, const float* __restrict__ ea,
                       const float* __restrict__ x, int E, int N) {
    C20 c;
    #pragma unroll
    for (int h = 0; h < 4; h++) {
        c.s0[h] = g_consts[h];
        c.s1[h] = g_consts[4 + h];
        c.d0[h] = g_consts[8 + h];
        c.d1[h] = g_consts[12 + h];
        c.g[h]  = g_consts[16 + h];
    }
    const float2* x2 = (const float2*)x;
    int base = blockIdx.x * (blockDim.x * 2) + threadIdx.x;
    int e0 = base, e1 = base + blockDim.x;
    float wsum = 0.f;

    int s0 = 0, d0 = 0, s1 = 0, d1 = 0;
    float w0 = 0.f, w1 = 0.f;
    bool v0 = e0 < E, v1 = e1 < E;
    if (v0) { s0 = __ldg(&ei[e0]); d0 = __ldg(&ei[E + e0]); w0 = __ldg(&ea[e0]); }
    if (v1) { s1 = __ldg(&ei[e1]); d1 = __ldg(&ei[E + e1]); w1 = __ldg(&ea[e1]); }
    if (v0) { wsum += w0; edge_body(x2, s0, d0, w0, N, c); }
    if (v1) { wsum += w1; edge_body(x2, s1, d1, w1, N, c); }

    #pragma unroll
    for (int o = 16; o; o >>= 1) wsum += __shfl_down_sync(0xffffffffu, wsum, o);
    __shared__ float sh[8];
    if ((threadIdx.x & 31) == 0) sh[threadIdx.x >> 5] = wsum;
    __syncthreads();
    if (threadIdx.x == 0) {
        float s = 0.f;
        #pragma unroll
        for (int i = 0; i < 8; i++) s += sh[i];
        atomicAdd(&g_easum, s);
    }
}

// K2: per-node expansion to [N, 256]; self-loop folded analytically.
// 64 threads/node row (float4 stores), block covers 4 nodes.
__global__ void k_out(const float* __restrict__ W, const float* __restrict__ bias,
                      const float* __restrict__ x, float* __restrict__ out,
                      int N, float invE) {
    int t = threadIdx.x;
    int sub = t & 63;
    int h = sub >> 4;            // hc0 = sub*4; h = hc0/64 = sub/16
    const float4* W4 = (const float4*)W;
    float4 wa = W4[sub * 2];
    float4 wb = W4[sub * 2 + 1];
    float4 b4 = ((const float4*)bias)[sub];
    float mean = g_easum * invE;
    float s0 = g_consts[h], s1 = g_consts[4 + h];
    float d0 = g_consts[8 + h], d1 = g_consts[12 + h];
    float gh = g_consts[16 + h];

    int n = blockIdx.x * 4 + (t >> 6);
    if (n >= N) return;

    float2 xn = ((const float2*)x)[n];
    float4 dd4 = g_accum[n * 3 + 0];
    float4 t04 = g_accum[n * 3 + 1];
    float4 t14 = g_accum[n * 3 + 2];
    float dh  = (h == 0) ? dd4.x : (h == 1) ? dd4.y : (h == 2) ? dd4.z : dd4.w;
    float t0h = (h == 0) ? t04.x : (h == 1) ? t04.y : (h == 2) ? t04.z : t04.w;
    float t1h = (h == 0) ? t14.x : (h == 1) ? t14.y : (h == 2) ? t14.z : t14.w;

    // self-loop logit: a_src[n,h] + a_dst[n,h] + mean*g[h]
    float a = xn.x * s0 + xn.y * s1 + xn.x * d0 + xn.y * d1 + mean * gh;
    a = fmaxf(a, 0.2f * a);
    float ws = __expf(a);
    float rdenom = 1.0f / (dh + ws);
    float T0 = (t0h + ws * xn.x) * rdenom;
    float T1 = (t1h + ws * xn.y) * rdenom;

    float4 o;
    o.x = T0 * wa.x + T1 * wa.y + b4.x;
    o.y = T0 * wa.z + T1 * wa.w + b4.y;
    o.z = T0 * wb.x + T1 * wb.y + b4.z;
    o.w = T0 * wb.z + T1 * wb.w + b4.w;
    ((float4*)out)[(size_t)n * 64 + sub] = o;
}

extern "C" void kernel_launch(void* const* d_in, const int* in_sizes, int n_in,
                              void* d_out, int out_size) {
    const float* x        = (const float*)d_in[0];
    const int*   ei       = (const int*)d_in[1];     // int32 (JAX x64 off)
    const float* ea       = (const float*)d_in[2];
    const float* W        = (const float*)d_in[3];
    const float* att_src  = (const float*)d_in[4];
    const float* att_dst  = (const float*)d_in[5];
    const float* W_edge   = (const float*)d_in[6];
    const float* att_edge = (const float*)d_in[7];
    const float* bias     = (const float*)d_in[8];
    int N = in_sizes[0] / 2;
    int E = in_sizes[2];
    float* out = (float*)d_out;

    k_init<<<592, 256>>>(W, att_src, att_dst, W_edge, att_edge);
    k_edge<<<(E + 511) / 512, 256>>>(ei, ea, x, E, N);
    k_out<<<(N + 3) / 4, 256>>>(W, bias, x, out, N, 1.0f / (float)E);
}